// round 3
// baseline (speedup 1.0000x reference)
#include <cuda_runtime.h>
#include <math.h>

// ---------------- problem constants ----------------
#define NN   128
#define CIN  64
#define CO   64
#define TT   128
#define VV   25
#define KK   3
#define GG   8
#define RR   8
#define DD   192            // CO * KK
#define TVV  (TT*VV)        // 3200
#define MTOT ((double)NN*TT*VV)  // 409600 samples per channel

// ---------------- scratch (static device arrays; no cudaMalloc) ----------------
__device__ float  g_xm  [NN*CIN*VV];                 // mean over T of x0        [n,c,v]
__device__ double g_Exx [CIN*CIN];                   // sum over (n,t,v) of x_c x_c'
__device__ float  g_Wp  [CIN*DD];                    // BN0-folded linear weight [c][d]
__device__ float  g_bp  [DD];                        // BN0-folded bias
__device__ float  g_nA  [KK*GG*VV*VV];               // column-normalized DecoupleA
__device__ float  g_x1  [KK*NN*RR*VV];
__device__ float  g_x2  [KK*NN*RR*VV];
__device__ float  g_att [(size_t)KK*NN*CO*VV*VV];    // 61.4 MB
__device__ float  g_xdec[(size_t)NN*CO*TT*VV];       // 105 MB
__device__ float  g_y   [(size_t)NN*CO*TT*VV];       // 105 MB
__device__ float  g_ens [(size_t)NN*CO*TT*VV];       // 105 MB
__device__ double g_s1[CO], g_s2[CO];
__device__ float  g_scale2[CO], g_shift2[CO];

// ---------------- K0: zero atomically-accumulated stats ----------------
__global__ void k0_zero() {
    int i = blockIdx.x * blockDim.x + threadIdx.x;
    if (i < CIN*CIN) g_Exx[i] = 0.0;
    if (i < CO) { g_s1[i] = 0.0; g_s2[i] = 0.0; }
}

// ---------------- K2: second moment Exx AND per-(n,c,v) T-mean, one x0 pass ----------------
// block per n, 256 threads. Tile = 4 timesteps: xs[64][100].
__global__ void k2_exx(const float* __restrict__ x0) {
    __shared__ float xs[CIN*100];         // 25.6 KB
    int n  = blockIdx.x;
    int tid = threadIdx.x;
    int ty = tid >> 4, tx = tid & 15;     // 16x16 grid of 4x4 output tiles

    float acc[4][4];
    #pragma unroll
    for (int i = 0; i < 4; i++)
        #pragma unroll
        for (int j = 0; j < 4; j++) acc[i][j] = 0.f;

    float macc[7];
    #pragma unroll
    for (int j = 0; j < 7; j++) macc[j] = 0.f;

    for (int tb = 0; tb < TT; tb += 4) {
        __syncthreads();
        for (int i = tid; i < CIN*25; i += 256) {
            int c = i / 25, q = i % 25;
            *(float4*)&xs[c*100 + q*4] =
                *(const float4*)&x0[((size_t)(n*CIN + c))*TVV + tb*VV + q*4];
        }
        __syncthreads();
        #pragma unroll 5
        for (int s4 = 0; s4 < 25; s4++) {
            float4 av[4], bv[4];
            #pragma unroll
            for (int i = 0; i < 4; i++) av[i] = *(float4*)&xs[(ty*4+i)*100 + s4*4];
            #pragma unroll
            for (int j = 0; j < 4; j++) bv[j] = *(float4*)&xs[(tx*4+j)*100 + s4*4];
            #pragma unroll
            for (int i = 0; i < 4; i++)
                #pragma unroll
                for (int j = 0; j < 4; j++) {
                    acc[i][j] += av[i].x*bv[j].x + av[i].y*bv[j].y
                               + av[i].z*bv[j].z + av[i].w*bv[j].w;
                }
        }
        #pragma unroll
        for (int j = 0; j < 7; j++) {
            int cell = tid + j*256;
            if (cell < CIN*VV) {
                int c = cell / VV, v = cell % VV;
                const float* row = &xs[c*100 + v];
                macc[j] += row[0] + row[25] + row[50] + row[75];
            }
        }
    }
    #pragma unroll
    for (int i = 0; i < 4; i++)
        #pragma unroll
        for (int j = 0; j < 4; j++)
            atomicAdd(&g_Exx[(ty*4+i)*CIN + (tx*4+j)], (double)acc[i][j]);
    #pragma unroll
    for (int j = 0; j < 7; j++) {
        int cell = tid + j*256;
        if (cell < CIN*VV) g_xm[n*CIN*VV + cell] = macc[j] * (1.0f/TT);
    }
}

// ---------------- K3: fold BN0 into linear; normalize adjacency ----------------
__global__ void k3_prep(const float* __restrict__ dA, const float* __restrict__ Lw,
                        const float* __restrict__ Lb, const float* __restrict__ g0,
                        const float* __restrict__ be0) {
    __shared__ float Ex[CIN];
    for (int c = threadIdx.x; c < CIN; c += blockDim.x) {
        float s = 0.f;
        for (int n = 0; n < NN; n++) {
            const float* p = &g_xm[(n*CIN + c)*VV];
            for (int v = 0; v < VV; v++) s += p[v];
        }
        Ex[c] = s / (float)(NN*VV);
    }
    __syncthreads();

    for (int d = threadIdx.x; d < DD; d += blockDim.x) {
        float w[CIN];
        for (int c = 0; c < CIN; c++) w[c] = Lw[c*DD + d];
        double m1 = 0.0;
        for (int c = 0; c < CIN; c++) m1 += (double)w[c] * Ex[c];
        double quad = 0.0;
        for (int c1 = 0; c1 < CIN; c1++) {
            double tsum = 0.0;
            const double* row = &g_Exx[c1*CIN];
            for (int c2 = 0; c2 < CIN; c2++) tsum += (double)w[c2] * row[c2];
            quad += (double)w[c1] * (tsum / MTOT);
        }
        double var = quad - m1*m1;                 // Var(x.W) == Var(x.W + b)
        float  s   = g0[d] * rsqrtf((float)var + 1e-5f);
        g_bp[d] = be0[d] - s * (float)m1;          // Lb cancels in (y - mu)
        for (int c = 0; c < CIN; c++) g_Wp[c*DD + d] = w[c] * s;
    }

    // column-normalized adjacency: nA[k,g,u,w] = dA / (colsum_w + 1e-3)
    for (int col = threadIdx.x; col < KK*GG*VV; col += blockDim.x) {
        int kg = col / VV, w = col % VV;
        float s = 0.f;
        for (int u = 0; u < VV; u++) s += dA[kg*VV*VV + u*VV + w];
        float inv = 1.0f / (s + 1e-3f);
        for (int u = 0; u < VV; u++)
            g_nA[kg*VV*VV + u*VV + w] = dA[kg*VV*VV + u*VV + w] * inv;
    }
}

// ---------------- K4: x1/x2 = xm . w1/w2 + b  (block per (k,n)) ----------------
__global__ void k4_x12(const float* __restrict__ w1, const float* __restrict__ b1,
                       const float* __restrict__ w2, const float* __restrict__ b2) {
    int kn = blockIdx.x, k = kn / NN, n = kn % NN;
    __shared__ float xms[CIN*VV];
    for (int i = threadIdx.x; i < CIN*VV; i += blockDim.x) xms[i] = g_xm[n*CIN*VV + i];
    __syncthreads();
    for (int idx = threadIdx.x; idx < RR*VV; idx += blockDim.x) {
        int r = idx / VV, u = idx % VV;
        float a1 = b1[k*RR + r], a2 = b2[k*RR + r];
        const float* w1r = &w1[(k*RR + r)*CIN];
        const float* w2r = &w2[(k*RR + r)*CIN];
        for (int c = 0; c < CIN; c++) {
            float xv = xms[c*VV + u];
            a1 += xv * w1r[c];
            a2 += xv * w2r[c];
        }
        g_x1[(size_t)kn*RR*VV + idx] = a1;
        g_x2[(size_t)kn*RR*VV + idx] = a2;
    }
}

// ---------------- K5: att[k,n,c,u,w] = alpha*(sum_r w4*tanh(x1_u - x2_w) + b4) + A ----------------
__global__ void k5_att(const float* __restrict__ w4, const float* __restrict__ b4,
                       const float* __restrict__ A,  const float* __restrict__ alp) {
    int kn = blockIdx.x, k = kn / NN;
    __shared__ float x1s[RR*VV], x2s[RR*VV], w4s[CO*RR], b4s[CO], As[VV*VV];
    __shared__ float Ds[VV*VV*RR];        // D[uw][r], 20 KB
    for (int i = threadIdx.x; i < RR*VV; i += blockDim.x) {
        x1s[i] = g_x1[(size_t)kn*RR*VV + i];
        x2s[i] = g_x2[(size_t)kn*RR*VV + i];
    }
    for (int i = threadIdx.x; i < CO*RR;  i += blockDim.x) w4s[i] = w4[k*CO*RR + i];
    for (int i = threadIdx.x; i < CO;     i += blockDim.x) b4s[i] = b4[k*CO + i];
    for (int i = threadIdx.x; i < VV*VV;  i += blockDim.x) As[i]  = A[k*VV*VV + i];
    __syncthreads();
    for (int i = threadIdx.x; i < VV*VV*RR; i += blockDim.x) {
        int uw = i / RR, r = i % RR;
        int u = uw / VV, w = uw % VV;
        Ds[i] = tanhf(x1s[r*VV + u] - x2s[r*VV + w]);
    }
    __syncthreads();
    float alpha = alp[0];
    float* attp = g_att + (size_t)kn*CO*VV*VV;
    for (int i = threadIdx.x; i < CO*VV*VV; i += blockDim.x) {
        int c = i / (VV*VV), uw = i % (VV*VV);
        float s = 0.f;
        #pragma unroll
        for (int r = 0; r < RR; r++) s += w4s[c*RR + r] * Ds[uw*RR + r];
        attp[i] = alpha * (s + b4s[c]) + As[uw];
    }
}

// ---------------- K6: CTRGC branch, fused x3 + att contraction ----------------
// grid (TT/8, NN), 512 thr.  y[n,c,t,v] = sum_k sum_u att[k,n,c,u,v] * x3_k[n,c,t,u]
// x3s stored TRANSPOSED: x3s[c*200 + u*8 + t] so the t-vector is contiguous.
__global__ void k6_y(const float* __restrict__ x0, const float* __restrict__ w3,
                     const float* __restrict__ b3) {
    extern __shared__ float sh[];
    float* xs  = sh;                  // [64][200]  x0 tile (s = t*25+v, contiguous)
    float* x3s = sh + CIN*200;        // [64][200]  transposed x3 tile: [c][u][t]
    float* w3s = sh + 2*CIN*200;      // [64][64]

    int n  = blockIdx.y;
    int tb = blockIdx.x * 8;
    int tid = threadIdx.x;

    for (int i = tid; i < CIN*50; i += 512) {
        int c = i / 50, q = i % 50;
        *(float4*)&xs[c*200 + q*4] =
            *(const float4*)&x0[((size_t)(n*CIN + c))*TVV + tb*VV + q*4];
    }

    float yacc[4][8];
    #pragma unroll
    for (int j = 0; j < 4; j++)
        #pragma unroll
        for (int t = 0; t < 8; t++) yacc[j][t] = 0.f;

    for (int k = 0; k < KK; k++) {
        __syncthreads();   // (k==0: xs ready; k>0: done reading x3s/w3s)
        for (int i = tid; i < CO*CIN; i += 512) w3s[i] = w3[k*CO*CIN + i];
        __syncthreads();
        // x3 stage, 4x4 register tile: rows c0,+16,+32,+48 share one float4 x-load
        for (int i = tid; i < 16*50; i += 512) {
            int c0 = i / 50, q = i % 50, s0 = q*4;
            float4 a[4];
            #pragma unroll
            for (int r = 0; r < 4; r++) a[r] = make_float4(0.f,0.f,0.f,0.f);
            #pragma unroll 4
            for (int ci = 0; ci < CIN; ci++) {
                float4 xv = *(float4*)&xs[ci*200 + s0];
                #pragma unroll
                for (int r = 0; r < 4; r++) {
                    float w = w3s[(c0 + r*16)*CIN + ci];
                    a[r].x += w*xv.x; a[r].y += w*xv.y;
                    a[r].z += w*xv.z; a[r].w += w*xv.w;
                }
            }
            #pragma unroll
            for (int r = 0; r < 4; r++) {
                int c = c0 + r*16;
                float bb = b3[k*CO + c];
                float vals[4] = {a[r].x, a[r].y, a[r].z, a[r].w};
                #pragma unroll
                for (int e = 0; e < 4; e++) {
                    int s = s0 + e, t = s / VV, v = s % VV;
                    x3s[c*200 + v*8 + t] = vals[e] + bb;
                }
            }
        }
        __syncthreads();
        // attention contraction: yacc[t] += att[c][u][v] * x3s[c][u][t]
        const float* attp = g_att + (size_t)(k*NN + n)*CO*VV*VV;
        #pragma unroll
        for (int j = 0; j < 4; j++) {
            int p = j*512 + tid;
            if (p < CO*VV) {
                int c = p / VV, v = p % VV;
                const float* ac = attp + c*VV*VV + v;   // stride VV over u
                const float* xc = x3s + c*200;
                #pragma unroll 5
                for (int u = 0; u < VV; u++) {
                    float a = ac[u*VV];
                    float4 xlo = *(float4*)&xc[u*8];
                    float4 xhi = *(float4*)&xc[u*8 + 4];
                    yacc[j][0] += a*xlo.x; yacc[j][1] += a*xlo.y;
                    yacc[j][2] += a*xlo.z; yacc[j][3] += a*xlo.w;
                    yacc[j][4] += a*xhi.x; yacc[j][5] += a*xhi.y;
                    yacc[j][6] += a*xhi.z; yacc[j][7] += a*xhi.w;
                }
            }
        }
    }
    #pragma unroll
    for (int j = 0; j < 4; j++) {
        int p = j*512 + tid;
        if (p < CO*VV) {
            int c = p / VV, v = p % VV;
            #pragma unroll
            for (int t = 0; t < 8; t++)
                g_y[((size_t)(n*CO + c))*TVV + (tb + t)*VV + v] = yacc[j][t];
        }
    }
}

// ---------------- K7: fused linear + BN0 + decouple adjacency ----------------
// grid (TT/4, NN), 512 thr.
__global__ void k7_dec(const float* __restrict__ x0) {
    extern __shared__ float sh[];
    float* xs   = sh;                       // [64][100]
    float* y192 = sh + CIN*100;             // [192][100]
    float* Wps  = y192 + DD*100;            // [64][192]
    float* bps  = Wps + CIN*DD;             // [192]
    float* nAs  = bps + DD;                 // [3*8*25*25]

    int n  = blockIdx.y;
    int tb = blockIdx.x * 4;
    int tid = threadIdx.x;

    for (int i = tid; i < CIN*25; i += 512) {
        int c = i / 25, q = i % 25;
        *(float4*)&xs[c*100 + q*4] =
            *(const float4*)&x0[((size_t)(n*CIN + c))*TVV + tb*VV + q*4];
    }
    for (int i = tid; i < CIN*DD; i += 512) Wps[i] = g_Wp[i];
    for (int i = tid; i < DD;     i += 512) bps[i] = g_bp[i];
    for (int i = tid; i < KK*GG*VV*VV; i += 512) nAs[i] = g_nA[i];
    __syncthreads();

    // y192 GEMM, 4x4 register tile: rows d0,+48,+96,+144 share one float4 x-load
    for (int i = tid; i < 48*25; i += 512) {
        int d0 = i / 25, q = i % 25, s0 = q*4;
        float4 a[4];
        #pragma unroll
        for (int r = 0; r < 4; r++) a[r] = make_float4(0.f,0.f,0.f,0.f);
        #pragma unroll 4
        for (int c = 0; c < CIN; c++) {
            float4 xv = *(float4*)&xs[c*100 + s0];
            #pragma unroll
            for (int r = 0; r < 4; r++) {
                float w = Wps[c*DD + d0 + r*48];
                a[r].x += w*xv.x; a[r].y += w*xv.y;
                a[r].z += w*xv.z; a[r].w += w*xv.w;
            }
        }
        #pragma unroll
        for (int r = 0; r < 4; r++) {
            int d = d0 + r*48;
            float bb = bps[d];
            a[r].x += bb; a[r].y += bb; a[r].z += bb; a[r].w += bb;
            *(float4*)&y192[d*100 + s0] = a[r];
        }
    }
    __syncthreads();

    // xdec[c][t][w] = sum_k sum_v y192[k*64+c][t*25+v] * nA[k][c&7][v][w]
    // rows (c0, c0+32) share the same adjacency group (c&7)
    for (int i = tid; i < 32*100; i += 512) {
        int c0 = i / 100, tw = i % 100, t = tw / VV, w = tw % VV;
        int g = c0 & 7;
        float a0 = 0.f, a1 = 0.f;
        #pragma unroll
        for (int k = 0; k < KK; k++) {
            const float* yp0 = &y192[(k*CO + c0)*100 + t*VV];
            const float* yp1 = &y192[(k*CO + c0 + 32)*100 + t*VV];
            const float* ap  = &nAs[(k*GG + g)*VV*VV + w];
            #pragma unroll 5
            for (int v = 0; v < VV; v++) {
                float av = ap[v*VV];
                a0 += yp0[v] * av;
                a1 += yp1[v] * av;
            }
        }
        g_xdec[((size_t)(n*CO + c0))*TVV + tb*VV + tw]      = a0;
        g_xdec[((size_t)(n*CO + c0 + 32))*TVV + tb*VV + tw] = a1;
    }
}

// ---------------- K8: ensemble GEMM + BN2 partial stats ----------------
// grid (TT/8, NN), 512 thr.  Fixed mapping: 16 threads per o-pair (o0, o0+32).
__global__ void k8_ens(const float* __restrict__ ew, const float* __restrict__ eb) {
    extern __shared__ float sh[];
    float* xd  = sh;                 // [64][200]
    float* ys  = sh + CIN*200;       // [64][200]
    float* ews = sh + 2*CIN*200;     // [64][128]
    float* s1s = ews + CO*2*CO;      // [64]
    float* s2s = s1s + CO;           // [64]

    int n  = blockIdx.y;
    int tb = blockIdx.x * 8;
    int tid = threadIdx.x;

    for (int i = tid; i < CIN*50; i += 512) {
        int c = i / 50, q = i % 50;
        size_t off = ((size_t)(n*CO + c))*TVV + tb*VV + q*4;
        *(float4*)&xd[c*200 + q*4] = *(const float4*)&g_xdec[off];
        *(float4*)&ys[c*200 + q*4] = *(const float4*)&g_y[off];
    }
    for (int i = tid; i < CO*2*CO; i += 512) ews[i] = ew[i];
    __syncthreads();

    int o0  = tid >> 4;              // 0..31 -> handles rows o0 and o0+32
    int sub = tid & 15;              // 16 threads per o-pair
    const float* wx0 = &ews[o0*2*CO];
    const float* wy0 = wx0 + CO;
    const float* wx1 = &ews[(o0+32)*2*CO];
    const float* wy1 = wx1 + CO;
    float bo0 = eb[o0], bo1 = eb[o0+32];
    size_t base0 = ((size_t)(n*CO + o0))*TVV + tb*VV;
    size_t base1 = ((size_t)(n*CO + o0 + 32))*TVV + tb*VV;

    float ls1a = 0.f, ls2a = 0.f, ls1b = 0.f, ls2b = 0.f;
    for (int j = 0; j < 4; j++) {
        int q = j*16 + sub;          // monotone in j, so break is safe
        if (q >= 50) break;
        int s0 = q*4;
        float4 A0 = {bo0, bo0, bo0, bo0};
        float4 A1 = {bo1, bo1, bo1, bo1};
        #pragma unroll 4
        for (int c = 0; c < CIN; c++) {
            float4 xv = *(float4*)&xd[c*200 + s0];
            float4 yv = *(float4*)&ys[c*200 + s0];
            float a0 = wx0[c], a1 = wy0[c], a2 = wx1[c], a3 = wy1[c];
            A0.x += a0*xv.x + a1*yv.x;  A0.y += a0*xv.y + a1*yv.y;
            A0.z += a0*xv.z + a1*yv.z;  A0.w += a0*xv.w + a1*yv.w;
            A1.x += a2*xv.x + a3*yv.x;  A1.y += a2*xv.y + a3*yv.y;
            A1.z += a2*xv.z + a3*yv.z;  A1.w += a2*xv.w + a3*yv.w;
        }
        *(float4*)&g_ens[base0 + s0] = A0;
        *(float4*)&g_ens[base1 + s0] = A1;
        ls1a += A0.x + A0.y + A0.z + A0.w;
        ls2a += A0.x*A0.x + A0.y*A0.y + A0.z*A0.z + A0.w*A0.w;
        ls1b += A1.x + A1.y + A1.z + A1.w;
        ls2b += A1.x*A1.x + A1.y*A1.y + A1.z*A1.z + A1.w*A1.w;
    }
    // width-16 butterfly-free reduction (16 consecutive lanes share o0)
    #pragma unroll
    for (int off = 8; off; off >>= 1) {
        ls1a += __shfl_down_sync(0xffffffffu, ls1a, off, 16);
        ls2a += __shfl_down_sync(0xffffffffu, ls2a, off, 16);
        ls1b += __shfl_down_sync(0xffffffffu, ls1b, off, 16);
        ls2b += __shfl_down_sync(0xffffffffu, ls2b, off, 16);
    }
    if (sub == 0) {
        s1s[o0] = ls1a;  s2s[o0] = ls2a;
        s1s[o0 + 32] = ls1b;  s2s[o0 + 32] = ls2b;
    }
    __syncthreads();
    if (tid < CO) {
        atomicAdd(&g_s1[tid], (double)s1s[tid]);
        atomicAdd(&g_s2[tid], (double)s2s[tid]);
    }
}

// ---------------- K9: finalize BN2 ----------------
__global__ void k9_fin(const float* __restrict__ bng, const float* __restrict__ bnb) {
    int o = threadIdx.x;
    if (o < CO) {
        double mu  = g_s1[o] / MTOT;
        double var = g_s2[o] / MTOT - mu*mu;
        float sc = bng[o] * rsqrtf((float)var + 1e-5f);
        g_scale2[o] = sc;
        g_shift2[o] = bnb[o] - (float)mu * sc;
    }
}

// ---------------- K10: BN2 apply + residual + ReLU ----------------
__global__ void k10_out(const float* __restrict__ x0, float* __restrict__ out) {
    size_t total4 = (size_t)NN*CO*TT*VV / 4;
    for (size_t i4 = (size_t)blockIdx.x*blockDim.x + threadIdx.x; i4 < total4;
         i4 += (size_t)gridDim.x*blockDim.x) {
        size_t i = i4 * 4;
        int o = (int)((i / TVV) & (CO - 1));
        float sc = g_scale2[o], shf = g_shift2[o];
        float4 e = *(const float4*)&g_ens[i];
        float4 x = *(const float4*)&x0[i];
        float4 r;
        r.x = fmaxf(e.x*sc + shf + x.x, 0.f);
        r.y = fmaxf(e.y*sc + shf + x.y, 0.f);
        r.z = fmaxf(e.z*sc + shf + x.z, 0.f);
        r.w = fmaxf(e.w*sc + shf + x.w, 0.f);
        *(float4*)&out[i] = r;
    }
}

// ---------------- launch ----------------
extern "C" void kernel_launch(void* const* d_in, const int* in_sizes, int n_in,
                              void* d_out, int out_size) {
    const float* x0  = (const float*)d_in[0];
    const float* dA  = (const float*)d_in[1];
    const float* A   = (const float*)d_in[2];
    const float* alp = (const float*)d_in[3];
    const float* w1  = (const float*)d_in[4];
    const float* b1  = (const float*)d_in[5];
    const float* w2  = (const float*)d_in[6];
    const float* b2  = (const float*)d_in[7];
    const float* w3  = (const float*)d_in[8];
    const float* b3  = (const float*)d_in[9];
    const float* w4  = (const float*)d_in[10];
    const float* b4  = (const float*)d_in[11];
    const float* Lw  = (const float*)d_in[12];
    const float* Lb  = (const float*)d_in[13];
    const float* g0  = (const float*)d_in[14];
    const float* be0 = (const float*)d_in[15];
    const float* ew  = (const float*)d_in[16];
    const float* eb  = (const float*)d_in[17];
    const float* bng = (const float*)d_in[18];
    const float* bnb = (const float*)d_in[19];
    float* out = (float*)d_out;

    const int smem_k6 = (2*CIN*200 + CO*CIN) * 4;                           // 118784
    const int smem_k7 = (CIN*100 + DD*100 + CIN*DD + DD + KK*GG*VV*VV) * 4; // 212320
    const int smem_k8 = (2*CIN*200 + CO*2*CO + 2*CO) * 4;                   // 135680

    cudaFuncSetAttribute(k6_y,   cudaFuncAttributeMaxDynamicSharedMemorySize, smem_k6);
    cudaFuncSetAttribute(k7_dec, cudaFuncAttributeMaxDynamicSharedMemorySize, smem_k7);
    cudaFuncSetAttribute(k8_ens, cudaFuncAttributeMaxDynamicSharedMemorySize, smem_k8);

    k0_zero<<<16, 256>>>();
    k2_exx <<<NN, 256>>>(x0);
    k3_prep<<<1, 256>>>(dA, Lw, Lb, g0, be0);
    k4_x12 <<<KK*NN, 256>>>(w1, b1, w2, b2);
    k5_att <<<KK*NN, 256>>>(w4, b4, A, alp);
    k6_y   <<<dim3(TT/8, NN), 512, smem_k6>>>(x0, w3, b3);
    k7_dec <<<dim3(TT/4, NN), 512, smem_k7>>>(x0);
    k8_ens <<<dim3(TT/8, NN), 512, smem_k8>>>(ew, eb);
    k9_fin <<<1, 64>>>(bng, bnb);
    k10_out<<<4096, 256>>>(x0, out);
}

// round 6
// speedup vs baseline: 1.0371x; 1.0371x over previous
#include <cuda_runtime.h>
#include <cuda_bf16.h>
#include <math.h>

// ---------------- problem constants ----------------
#define NN   128
#define CIN  64
#define CO   64
#define TT   128
#define VV   25
#define KK   3
#define GG   8
#define RR   8
#define DD   192            // CO * KK
#define TVV  (TT*VV)        // 3200
#define MTOT ((double)NN*TT*VV)  // 409600 samples per channel

typedef unsigned long long ull;

// packed f32x2 helpers (Blackwell sm_103a)
__device__ __forceinline__ void ffma2(ull &d, ull a, ull b) {
    asm("fma.rn.f32x2 %0, %1, %2, %3;" : "=l"(d) : "l"(a), "l"(b), "l"(d));
}
__device__ __forceinline__ ull dup2(float x) {
    ull r; asm("mov.b64 %0, {%1, %1};" : "=l"(r) : "f"(x)); return r;
}
__device__ __forceinline__ float2 unpk(ull v) {
    float2 f; asm("mov.b64 {%0, %1}, %2;" : "=f"(f.x), "=f"(f.y) : "l"(v)); return f;
}
__device__ __forceinline__ void hfma2(unsigned &d, unsigned a, unsigned b) {
    asm("fma.rn.bf16x2 %0, %1, %2, %3;" : "=r"(d) : "r"(a), "r"(b), "r"(d));
}

// ---------------- scratch (static device arrays; no cudaMalloc) ----------------
__device__ float  g_xm  [NN*CIN*VV];
__device__ double g_Exx [CIN*CIN];
__device__ float  g_Wp  [CIN*DD];                    // BN0-folded linear weight [c][d]
__device__ float  g_bp  [DD];
__device__ __nv_bfloat162 g_nAT2[KK*GG*VV*13];       // transposed packed norm-adjacency
__device__ float  g_x1  [KK*NN*RR*VV];
__device__ float  g_x2  [KK*NN*RR*VV];
__device__ float  g_att [(size_t)KK*NN*CO*VV*VV];    // 61.4 MB
__device__ float  g_xdec[(size_t)NN*CO*TT*VV];       // 105 MB
__device__ float  g_y   [(size_t)NN*CO*TT*VV];       // 105 MB
__device__ float  g_ens [(size_t)NN*CO*TT*VV];       // 105 MB
__device__ double g_s1[CO], g_s2[CO];
__device__ float  g_scale2[CO], g_shift2[CO];

// ---------------- K0 ----------------
__global__ void k0_zero() {
    int i = blockIdx.x * blockDim.x + threadIdx.x;
    if (i < CIN*CIN) g_Exx[i] = 0.0;
    if (i < CO) { g_s1[i] = 0.0; g_s2[i] = 0.0; }
}

// ---------------- K2: Exx + T-mean, one x0 pass (block per n, 256 thr) ----------------
__global__ void k2_exx(const float* __restrict__ x0) {
    __shared__ float xs[CIN*100];
    int n  = blockIdx.x;
    int tid = threadIdx.x;
    int ty = tid >> 4, tx = tid & 15;

    ull pacc[4][4];
    #pragma unroll
    for (int i = 0; i < 4; i++)
        #pragma unroll
        for (int j = 0; j < 4; j++) pacc[i][j] = 0ull;

    float macc[7];
    #pragma unroll
    for (int j = 0; j < 7; j++) macc[j] = 0.f;

    for (int tb = 0; tb < TT; tb += 4) {
        __syncthreads();
        for (int i = tid; i < CIN*25; i += 256) {
            int c = i / 25, q = i % 25;
            *(float4*)&xs[c*100 + q*4] =
                *(const float4*)&x0[((size_t)(n*CIN + c))*TVV + tb*VV + q*4];
        }
        __syncthreads();
        #pragma unroll 5
        for (int s4 = 0; s4 < 25; s4++) {
            ulonglong2 av[4], bv[4];
            #pragma unroll
            for (int i = 0; i < 4; i++) av[i] = *(ulonglong2*)&xs[(ty*4+i)*100 + s4*4];
            #pragma unroll
            for (int j = 0; j < 4; j++) bv[j] = *(ulonglong2*)&xs[(tx*4+j)*100 + s4*4];
            #pragma unroll
            for (int i = 0; i < 4; i++)
                #pragma unroll
                for (int j = 0; j < 4; j++) {
                    ffma2(pacc[i][j], av[i].x, bv[j].x);
                    ffma2(pacc[i][j], av[i].y, bv[j].y);
                }
        }
        #pragma unroll
        for (int j = 0; j < 7; j++) {
            int cell = tid + j*256;
            if (cell < CIN*VV) {
                int c = cell / VV, v = cell % VV;
                const float* row = &xs[c*100 + v];
                macc[j] += row[0] + row[25] + row[50] + row[75];
            }
        }
    }
    #pragma unroll
    for (int i = 0; i < 4; i++)
        #pragma unroll
        for (int j = 0; j < 4; j++) {
            float2 f = unpk(pacc[i][j]);
            atomicAdd(&g_Exx[(ty*4+i)*CIN + (tx*4+j)], (double)(f.x + f.y));
        }
    #pragma unroll
    for (int j = 0; j < 7; j++) {
        int cell = tid + j*256;
        if (cell < CIN*VV) g_xm[n*CIN*VV + cell] = macc[j] * (1.0f/TT);
    }
}

// ---------------- K3: fold BN0 into linear; build transposed packed adjacency ----------------
__global__ void k3_prep(const float* __restrict__ dA, const float* __restrict__ Lw,
                        const float* __restrict__ Lb, const float* __restrict__ g0,
                        const float* __restrict__ be0) {
    __shared__ float Ex[CIN];
    for (int c = threadIdx.x; c < CIN; c += blockDim.x) {
        float s = 0.f;
        for (int n = 0; n < NN; n++) {
            const float* p = &g_xm[(n*CIN + c)*VV];
            for (int v = 0; v < VV; v++) s += p[v];
        }
        Ex[c] = s / (float)(NN*VV);
    }
    __syncthreads();

    for (int d = threadIdx.x; d < DD; d += blockDim.x) {
        float w[CIN];
        for (int c = 0; c < CIN; c++) w[c] = Lw[c*DD + d];
        double m1 = 0.0;
        for (int c = 0; c < CIN; c++) m1 += (double)w[c] * Ex[c];
        double quad = 0.0;
        for (int c1 = 0; c1 < CIN; c1++) {
            double tsum = 0.0;
            const double* row = &g_Exx[c1*CIN];
            for (int c2 = 0; c2 < CIN; c2++) tsum += (double)w[c2] * row[c2];
            quad += (double)w[c1] * (tsum / MTOT);
        }
        double var = quad - m1*m1;
        float  s   = g0[d] * rsqrtf((float)var + 1e-5f);
        g_bp[d] = be0[d] - s * (float)m1;
        for (int c = 0; c < CIN; c++) g_Wp[c*DD + d] = w[c] * s;
    }

    // nAT2[kg][w][p] = packed bf16x2 of (nA[kg][2p][w], nA[kg][2p+1][w]), pad v=25 -> 0
    for (int col = threadIdx.x; col < KK*GG*VV; col += blockDim.x) {
        int kg = col / VV, w = col % VV;
        float s = 0.f;
        for (int u = 0; u < VV; u++) s += dA[kg*VV*VV + u*VV + w];
        float inv = 1.0f / (s + 1e-3f);
        for (int p = 0; p < 13; p++) {
            float f0 = dA[kg*VV*VV + (2*p)*VV + w] * inv;
            float f1 = (2*p+1 < VV) ? dA[kg*VV*VV + (2*p+1)*VV + w] * inv : 0.f;
            g_nAT2[(kg*VV + w)*13 + p] = __floats2bfloat162_rn(f0, f1);
        }
    }
}

// ---------------- K4: x1/x2 = xm . w1/w2 + b ----------------
__global__ void k4_x12(const float* __restrict__ w1, const float* __restrict__ b1,
                       const float* __restrict__ w2, const float* __restrict__ b2) {
    int kn = blockIdx.x, k = kn / NN, n = kn % NN;
    __shared__ float xms[CIN*VV];
    for (int i = threadIdx.x; i < CIN*VV; i += blockDim.x) xms[i] = g_xm[n*CIN*VV + i];
    __syncthreads();
    for (int idx = threadIdx.x; idx < RR*VV; idx += blockDim.x) {
        int r = idx / VV, u = idx % VV;
        float a1 = b1[k*RR + r], a2 = b2[k*RR + r];
        const float* w1r = &w1[(k*RR + r)*CIN];
        const float* w2r = &w2[(k*RR + r)*CIN];
        for (int c = 0; c < CIN; c++) {
            float xv = xms[c*VV + u];
            a1 += xv * w1r[c];
            a2 += xv * w2r[c];
        }
        g_x1[(size_t)kn*RR*VV + idx] = a1;
        g_x2[(size_t)kn*RR*VV + idx] = a2;
    }
}

// ---------------- K5: attention matrices ----------------
__global__ void k5_att(const float* __restrict__ w4, const float* __restrict__ b4,
                       const float* __restrict__ A,  const float* __restrict__ alp) {
    int kn = blockIdx.x, k = kn / NN;
    __shared__ float x1s[RR*VV], x2s[RR*VV], w4s[CO*RR], b4s[CO], As[VV*VV];
    __shared__ float Ds[VV*VV*RR];
    for (int i = threadIdx.x; i < RR*VV; i += blockDim.x) {
        x1s[i] = g_x1[(size_t)kn*RR*VV + i];
        x2s[i] = g_x2[(size_t)kn*RR*VV + i];
    }
    for (int i = threadIdx.x; i < CO*RR;  i += blockDim.x) w4s[i] = w4[k*CO*RR + i];
    for (int i = threadIdx.x; i < CO;     i += blockDim.x) b4s[i] = b4[k*CO + i];
    for (int i = threadIdx.x; i < VV*VV;  i += blockDim.x) As[i]  = A[k*VV*VV + i];
    __syncthreads();
    for (int i = threadIdx.x; i < VV*VV*RR; i += blockDim.x) {
        int uw = i / RR, r = i % RR;
        int u = uw / VV, w = uw % VV;
        Ds[i] = tanhf(x1s[r*VV + u] - x2s[r*VV + w]);
    }
    __syncthreads();
    float alpha = alp[0];
    float* attp = g_att + (size_t)kn*CO*VV*VV;
    for (int i = threadIdx.x; i < CO*VV*VV; i += blockDim.x) {
        int c = i / (VV*VV), uw = i % (VV*VV);
        float s = 0.f;
        #pragma unroll
        for (int r = 0; r < RR; r++) s += w4s[c*RR + r] * Ds[uw*RR + r];
        attp[i] = alpha * (s + b4s[c]) + As[uw];
    }
}

// ---------------- K6: CTRGC branch (fused x3 GEMM + att contraction) ----------------
// grid (TT/8, NN), 512 thr. smem: xs[64][200] + x3s[64][200] + w3dup[64][64] f2
__global__ void __launch_bounds__(512, 1) k6_y(
        const float* __restrict__ x0, const float* __restrict__ w3,
        const float* __restrict__ b3) {
    extern __shared__ float sh[];
    float* xs  = sh;                         // 12800 f
    float* x3s = sh + 12800;                 // 12800 f, layout [c][u][t]
    ull*   w3d = (ull*)(sh + 25600);         // [64][64] duplicated pairs (8192 f)

    int n  = blockIdx.y;
    int tb = blockIdx.x * 8;
    int tid = threadIdx.x;

    for (int i = tid; i < CIN*50; i += 512) {
        int c = i / 50, q = i % 50;
        *(float4*)&xs[c*200 + q*4] =
            *(const float4*)&x0[((size_t)(n*CIN + c))*TVV + tb*VV + q*4];
    }

    ull ya[4][4];
    #pragma unroll
    for (int j = 0; j < 4; j++)
        #pragma unroll
        for (int e = 0; e < 4; e++) ya[j][e] = 0ull;

    for (int k = 0; k < KK; k++) {
        __syncthreads();
        for (int i = tid; i < CO*CIN; i += 512)
            w3d[i] = dup2(w3[k*CO*CIN + i]);
        __syncthreads();
        // x3 GEMM: 8 rows (c0 + r*8) per task, 4-wide s; tasks = 8*50 = 400
        if (tid < 400) {
            int c0 = tid / 50, q = tid % 50, s0 = q*4;
            ull a[8][2];
            #pragma unroll
            for (int r = 0; r < 8; r++) { a[r][0] = 0ull; a[r][1] = 0ull; }
            #pragma unroll 4
            for (int ci = 0; ci < CIN; ci++) {
                ulonglong2 xv = *(ulonglong2*)&xs[ci*200 + s0];
                #pragma unroll
                for (int r = 0; r < 8; r++) {
                    ull wd = w3d[(c0 + r*8)*CIN + ci];
                    ffma2(a[r][0], wd, xv.x);
                    ffma2(a[r][1], wd, xv.y);
                }
            }
            #pragma unroll
            for (int r = 0; r < 8; r++) {
                int c = c0 + r*8;
                float bb = b3[k*CO + c];
                float2 lo = unpk(a[r][0]), hi = unpk(a[r][1]);
                float vals[4] = {lo.x, lo.y, hi.x, hi.y};
                #pragma unroll
                for (int e = 0; e < 4; e++) {
                    int s = s0 + e, t = s / VV, v = s % VV;
                    x3s[c*200 + v*8 + t] = vals[e] + bb;
                }
            }
        }
        __syncthreads();
        // attention contraction: ya[t-pairs] += att[c][u][v] * x3s[c][u][:]
        const float* attp = g_att + (size_t)(k*NN + n)*CO*VV*VV;
        #pragma unroll
        for (int j = 0; j < 4; j++) {
            int p = j*512 + tid;
            if (p < CO*VV) {
                int c = p / VV, v = p % VV;
                const float* ac = attp + c*VV*VV + v;
                const float* xc = x3s + c*200;
                #pragma unroll 5
                for (int u = 0; u < VV; u++) {
                    ull ad = dup2(ac[u*VV]);
                    ulonglong2 xlo = *(ulonglong2*)&xc[u*8];
                    ulonglong2 xhi = *(ulonglong2*)&xc[u*8 + 4];
                    ffma2(ya[j][0], ad, xlo.x);
                    ffma2(ya[j][1], ad, xlo.y);
                    ffma2(ya[j][2], ad, xhi.x);
                    ffma2(ya[j][3], ad, xhi.y);
                }
            }
        }
    }
    #pragma unroll
    for (int j = 0; j < 4; j++) {
        int p = j*512 + tid;
        if (p < CO*VV) {
            int c = p / VV, v = p % VV;
            float2 f0 = unpk(ya[j][0]), f1 = unpk(ya[j][1]);
            float2 f2 = unpk(ya[j][2]), f3 = unpk(ya[j][3]);
            float tv[8] = {f0.x, f0.y, f1.x, f1.y, f2.x, f2.y, f3.x, f3.y};
            #pragma unroll
            for (int t = 0; t < 8; t++)
                g_y[((size_t)(n*CO + c))*TVV + (tb + t)*VV + v] = tv[t];
        }
    }
}

// ---------------- K7: fused linear + BN0 + decouple adjacency ----------------
// grid (TT/4, NN), 512 thr.
// smem: xsd dup [64][100] f2 | Wpp row-pair-packed [64][96] ull | y192h bf16 [192][4][26]
//       | nAT2 [600][13] u32 | bps[192]
__global__ void __launch_bounds__(512, 1) k7_dec(const float* __restrict__ x0) {
    extern __shared__ float sh[];
    float2* xsd   = (float2*)sh;                       // 12800 f
    ull*    Wpp   = (ull*)(sh + 12800);                // 12288 f
    __nv_bfloat16* y192h = (__nv_bfloat16*)(sh + 25088); // 9984 f
    unsigned* nAT2s = (unsigned*)(sh + 35072);         // 7800 f
    float*  bps   = sh + 42872;                        // 192 f

    int n  = blockIdx.y;
    int tb = blockIdx.x * 4;
    int tid = threadIdx.x;

    for (int i = tid; i < CIN*25; i += 512) {
        int c = i / 25, q = i % 25;
        float4 xv = *(const float4*)&x0[((size_t)(n*CIN + c))*TVV + tb*VV + q*4];
        int base = c*100 + q*4;
        xsd[base]   = make_float2(xv.x, xv.x);
        xsd[base+1] = make_float2(xv.y, xv.y);
        xsd[base+2] = make_float2(xv.z, xv.z);
        xsd[base+3] = make_float2(xv.w, xv.w);
    }
    for (int i = tid; i < CIN*96; i += 512) {
        int c = i / 96, d = i % 96;
        ((float2*)Wpp)[c*96 + d] = make_float2(g_Wp[c*DD + d], g_Wp[c*DD + d + 96]);
    }
    for (int i = tid; i < DD; i += 512) bps[i] = g_bp[i];
    for (int i = tid; i < KK*GG*VV*13; i += 512)
        nAT2s[i] = ((const unsigned*)g_nAT2)[i];
    for (int i = tid; i < DD*4; i += 512) {       // zero v=25 pad slots
        int d = i >> 2, t = i & 3;
        y192h[d*104 + t*26 + 25] = __float2bfloat16(0.f);
    }
    __syncthreads();

    // stage 1: y192 GEMM; 8 rows per task as 4 packed pairs (d0+p*24, +96); tasks = 24*25
    const ull* xsdu = (const ull*)xsd;
    for (int rep = 0; rep < 2; rep++) {
        int i = rep*512 + tid;
        if (i >= 24*25) break;
        int d0 = i / 25, q = i % 25, s0 = q*4;
        ull A[4][4];
        #pragma unroll
        for (int p = 0; p < 4; p++)
            #pragma unroll
            for (int e = 0; e < 4; e++) A[p][e] = 0ull;
        #pragma unroll 4
        for (int ci = 0; ci < CIN; ci++) {
            ulonglong2 xa = *(ulonglong2*)&xsdu[ci*100 + s0];
            ulonglong2 xb = *(ulonglong2*)&xsdu[ci*100 + s0 + 2];
            #pragma unroll
            for (int p = 0; p < 4; p++) {
                ull w = Wpp[ci*96 + d0 + p*24];
                ffma2(A[p][0], w, xa.x);
                ffma2(A[p][1], w, xa.y);
                ffma2(A[p][2], w, xb.x);
                ffma2(A[p][3], w, xb.y);
            }
        }
        #pragma unroll
        for (int p = 0; p < 4; p++) {
            int da = d0 + p*24, db = da + 96;
            float fa = bps[da], fb = bps[db];
            #pragma unroll
            for (int e = 0; e < 4; e++) {
                float2 f = unpk(A[p][e]);
                int s = s0 + e, t = s / VV, v = s % VV;
                y192h[da*104 + t*26 + v] = __float2bfloat16(f.x + fa);
                y192h[db*104 + t*26 + v] = __float2bfloat16(f.y + fb);
            }
        }
    }
    __syncthreads();

    // stage 2: xdec[c][t][w] = sum_k sum_v y192[kc][t][v] * nAT[kg][w][v]  (bf16x2)
    const unsigned* yu = (const unsigned*)y192h;
    for (int rep = 0; rep < 7; rep++) {
        int i = rep*512 + tid;
        if (i >= 32*100) break;
        int c0 = i / 100, tw = i % 100, t = tw / VV, w = tw % VV;
        int g = c0 & 7;
        unsigned h0 = 0, h1 = 0;
        #pragma unroll
        for (int k = 0; k < KK; k++) {
            const unsigned* nr = nAT2s + ((k*GG + g)*VV + w)*13;
            const unsigned* y0 = yu + (k*CO + c0)*52 + t*13;
            const unsigned* y1 = yu + (k*CO + c0 + 32)*52 + t*13;
            #pragma unroll
            for (int p = 0; p < 13; p++) {
                unsigned av = nr[p];
                hfma2(h0, av, y0[p]);
                hfma2(h1, av, y1[p]);
            }
        }
        __nv_bfloat162 hb0 = *(__nv_bfloat162*)&h0;
        __nv_bfloat162 hb1 = *(__nv_bfloat162*)&h1;
        g_xdec[((size_t)(n*CO + c0))*TVV + tb*VV + tw] =
            __low2float(hb0) + __high2float(hb0);
        g_xdec[((size_t)(n*CO + c0 + 32))*TVV + tb*VV + tw] =
            __low2float(hb1) + __high2float(hb1);
    }
}

// ---------------- K8: ensemble GEMM + BN2 partial stats ----------------
// grid (TT/8, NN), 512 thr. Each warp owns o-quad (wid, wid+16, wid+32, wid+48).
__global__ void __launch_bounds__(512, 1) k8_ens(
        const float* __restrict__ ew, const float* __restrict__ eb) {
    extern __shared__ float sh[];
    float* xd  = sh;                   // 12800 f
    float* ys  = sh + 12800;           // 12800 f
    ull*   ewd = (ull*)(sh + 25600);   // [64][128] dup (16384 f)
    float* s1s = sh + 41984;           // 64
    float* s2s = sh + 42048;           // 64

    int n  = blockIdx.y;
    int tb = blockIdx.x * 8;
    int tid = threadIdx.x;
    int wid = tid >> 5, lane = tid & 31;

    for (int i = tid; i < CIN*50; i += 512) {
        int c = i / 50, q = i % 50;
        size_t off = ((size_t)(n*CO + c))*TVV + tb*VV + q*4;
        *(float4*)&xd[c*200 + q*4] = *(const float4*)&g_xdec[off];
        *(float4*)&ys[c*200 + q*4] = *(const float4*)&g_y[off];
    }
    for (int i = tid; i < CO*2*CO; i += 512)
        ewd[i] = dup2(ew[i]);
    __syncthreads();

    int o[4];  ull bd[4];
    float ls1[4], ls2[4];
    #pragma unroll
    for (int r = 0; r < 4; r++) {
        o[r] = wid + r*16;
        bd[r] = dup2(eb[o[r]]);
        ls1[r] = 0.f; ls2[r] = 0.f;
    }

    for (int rep = 0; rep < 2; rep++) {
        int q = lane + rep*32;
        if (q >= 50) break;
        int s0 = q*4;
        ull A[4][2];
        #pragma unroll
        for (int r = 0; r < 4; r++) { A[r][0] = bd[r]; A[r][1] = bd[r]; }
        #pragma unroll 4
        for (int c = 0; c < CIN; c++) {
            ulonglong2 xv = *(ulonglong2*)&xd[c*200 + s0];
            ulonglong2 yv = *(ulonglong2*)&ys[c*200 + s0];
            #pragma unroll
            for (int r = 0; r < 4; r++) {
                ull wx = ewd[o[r]*128 + c];
                ull wy = ewd[o[r]*128 + 64 + c];
                ffma2(A[r][0], wx, xv.x);
                ffma2(A[r][0], wy, yv.x);
                ffma2(A[r][1], wx, xv.y);
                ffma2(A[r][1], wy, yv.y);
            }
        }
        #pragma unroll
        for (int r = 0; r < 4; r++) {
            float2 lo = unpk(A[r][0]), hi = unpk(A[r][1]);
            float4 res = make_float4(lo.x, lo.y, hi.x, hi.y);
            *(float4*)&g_ens[((size_t)(n*CO + o[r]))*TVV + tb*VV + s0] = res;
            ls1[r] += res.x + res.y + res.z + res.w;
            ls2[r] += res.x*res.x + res.y*res.y + res.z*res.z + res.w*res.w;
        }
    }
    // width-32 warp reduction; all lanes of a warp share the same o-quad
    #pragma unroll
    for (int off = 16; off; off >>= 1) {
        #pragma unroll
        for (int r = 0; r < 4; r++) {
            ls1[r] += __shfl_down_sync(0xffffffffu, ls1[r], off);
            ls2[r] += __shfl_down_sync(0xffffffffu, ls2[r], off);
        }
    }
    if (lane == 0) {
        #pragma unroll
        for (int r = 0; r < 4; r++) { s1s[o[r]] = ls1[r]; s2s[o[r]] = ls2[r]; }
    }
    __syncthreads();
    if (tid < CO) {
        atomicAdd(&g_s1[tid], (double)s1s[tid]);
        atomicAdd(&g_s2[tid], (double)s2s[tid]);
    }
}

// ---------------- K9: finalize BN2 ----------------
__global__ void k9_fin(const float* __restrict__ bng, const float* __restrict__ bnb) {
    int o = threadIdx.x;
    if (o < CO) {
        double mu  = g_s1[o] / MTOT;
        double var = g_s2[o] / MTOT - mu*mu;
        float sc = bng[o] * rsqrtf((float)var + 1e-5f);
        g_scale2[o] = sc;
        g_shift2[o] = bnb[o] - (float)mu * sc;
    }
}

// ---------------- K10: BN2 apply + residual + ReLU ----------------
__global__ void k10_out(const float* __restrict__ x0, float* __restrict__ out) {
    size_t total4 = (size_t)NN*CO*TT*VV / 4;
    for (size_t i4 = (size_t)blockIdx.x*blockDim.x + threadIdx.x; i4 < total4;
         i4 += (size_t)gridDim.x*blockDim.x) {
        size_t i = i4 * 4;
        int o = (int)((i / TVV) & (CO - 1));
        float sc = g_scale2[o], shf = g_shift2[o];
        float4 e = *(const float4*)&g_ens[i];
        float4 x = *(const float4*)&x0[i];
        float4 r;
        r.x = fmaxf(e.x*sc + shf + x.x, 0.f);
        r.y = fmaxf(e.y*sc + shf + x.y, 0.f);
        r.z = fmaxf(e.z*sc + shf + x.z, 0.f);
        r.w = fmaxf(e.w*sc + shf + x.w, 0.f);
        *(float4*)&out[i] = r;
    }
}

// ---------------- launch ----------------
extern "C" void kernel_launch(void* const* d_in, const int* in_sizes, int n_in,
                              void* d_out, int out_size) {
    const float* x0  = (const float*)d_in[0];
    const float* dA  = (const float*)d_in[1];
    const float* A   = (const float*)d_in[2];
    const float* alp = (const float*)d_in[3];
    const float* w1  = (const float*)d_in[4];
    const float* b1  = (const float*)d_in[5];
    const float* w2  = (const float*)d_in[6];
    const float* b2  = (const float*)d_in[7];
    const float* w3  = (const float*)d_in[8];
    const float* b3  = (const float*)d_in[9];
    const float* w4  = (const float*)d_in[10];
    const float* b4  = (const float*)d_in[11];
    const float* Lw  = (const float*)d_in[12];
    const float* Lb  = (const float*)d_in[13];
    const float* g0  = (const float*)d_in[14];
    const float* be0 = (const float*)d_in[15];
    const float* ew  = (const float*)d_in[16];
    const float* eb  = (const float*)d_in[17];
    const float* bng = (const float*)d_in[18];
    const float* bnb = (const float*)d_in[19];
    float* out = (float*)d_out;

    const int smem_k6 = (12800 + 12800 + 8192) * 4;            // 135168
    const int smem_k7 = 43064 * 4;                              // 172256
    const int smem_k8 = (12800 + 12800 + 16384 + 128) * 4;      // 168448

    cudaFuncSetAttribute(k6_y,   cudaFuncAttributeMaxDynamicSharedMemorySize, smem_k6);
    cudaFuncSetAttribute(k7_dec, cudaFuncAttributeMaxDynamicSharedMemorySize, smem_k7);
    cudaFuncSetAttribute(k8_ens, cudaFuncAttributeMaxDynamicSharedMemorySize, smem_k8);

    // k7 placed 4th so the ncu sampled launch is the biggest kernel
    k0_zero<<<16, 256>>>();
    k2_exx <<<NN, 256>>>(x0);
    k3_prep<<<1, 256>>>(dA, Lw, Lb, g0, be0);
    k7_dec <<<dim3(TT/4, NN), 512, smem_k7>>>(x0);
    k4_x12 <<<KK*NN, 256>>>(w1, b1, w2, b2);
    k5_att <<<KK*NN, 256>>>(w4, b4, A, alp);
    k6_y   <<<dim3(TT/8, NN), 512, smem_k6>>>(x0, w3, b3);
    k8_ens <<<dim3(TT/8, NN), 512, smem_k8>>>(ew, eb);
    k9_fin <<<1, 64>>>(bng, bnb);
    k10_out<<<4096, 256>>>(x0, out);
}

// round 8
// speedup vs baseline: 1.0584x; 1.0205x over previous
#include <cuda_runtime.h>
#include <cuda_bf16.h>
#include <math.h>

// ---------------- problem constants ----------------
#define NN   128
#define CIN  64
#define CO   64
#define TT   128
#define VV   25
#define KK   3
#define GG   8
#define RR   8
#define DD   192            // CO * KK
#define TVV  (TT*VV)        // 3200
#define MTOT ((double)NN*TT*VV)  // 409600 samples per channel

typedef unsigned long long ull;

// packed f32x2 helpers (Blackwell sm_103a)
__device__ __forceinline__ void ffma2(ull &d, ull a, ull b) {
    asm("fma.rn.f32x2 %0, %1, %2, %3;" : "=l"(d) : "l"(a), "l"(b), "l"(d));
}
__device__ __forceinline__ ull dup2(float x) {
    ull r; asm("mov.b64 %0, {%1, %1};" : "=l"(r) : "f"(x)); return r;
}
__device__ __forceinline__ float2 unpk(ull v) {
    float2 f; asm("mov.b64 {%0, %1}, %2;" : "=f"(f.x), "=f"(f.y) : "l"(v)); return f;
}
__device__ __forceinline__ void hfma2(unsigned &d, unsigned a, unsigned b) {
    asm("fma.rn.bf16x2 %0, %1, %2, %3;" : "=r"(d) : "r"(a), "r"(b), "r"(d));
}

// ---------------- scratch (static device arrays; no cudaMalloc) ----------------
__device__ float  g_xm  [NN*CIN*VV];
__device__ double g_Exxp[(size_t)NN*CIN*CIN];         // per-n second-moment partials
__device__ double g_Exx [CIN*CIN];
__device__ float  g_Wp  [CIN*DD];                     // BN0-folded linear weight [c][d]
__device__ float  g_bp  [DD];
__device__ __nv_bfloat162 g_nAT2[KK*GG*VV*13];        // transposed packed norm-adjacency
__device__ float  g_x1  [KK*NN*RR*VV];
__device__ float  g_x2  [KK*NN*RR*VV];
__device__ float  g_att [(size_t)KK*NN*CO*VV*VV];     // 61.4 MB
__device__ float  g_xdec[(size_t)NN*CO*TT*VV];        // 105 MB
__device__ float  g_y   [(size_t)NN*CO*TT*VV];        // 105 MB
__device__ float  g_ens [(size_t)NN*CO*TT*VV];        // 105 MB
__device__ double g_s1[CO], g_s2[CO];
__device__ float  g_scale2[CO], g_shift2[CO];

// ---------------- K2: per-n Exx partials + T-mean, one x0 pass (block per n) ----------------
__global__ void k2_exx(const float* __restrict__ x0) {
    __shared__ float xs[CIN*100];
    int n  = blockIdx.x;
    int tid = threadIdx.x;
    int ty = tid >> 4, tx = tid & 15;

    ull pacc[4][4];
    #pragma unroll
    for (int i = 0; i < 4; i++)
        #pragma unroll
        for (int j = 0; j < 4; j++) pacc[i][j] = 0ull;

    float macc[7];
    #pragma unroll
    for (int j = 0; j < 7; j++) macc[j] = 0.f;

    for (int tb = 0; tb < TT; tb += 4) {
        __syncthreads();
        for (int i = tid; i < CIN*25; i += 256) {
            int c = i / 25, q = i % 25;
            *(float4*)&xs[c*100 + q*4] =
                *(const float4*)&x0[((size_t)(n*CIN + c))*TVV + tb*VV + q*4];
        }
        __syncthreads();
        #pragma unroll 5
        for (int s4 = 0; s4 < 25; s4++) {
            ulonglong2 av[4], bv[4];
            #pragma unroll
            for (int i = 0; i < 4; i++) av[i] = *(ulonglong2*)&xs[(ty*4+i)*100 + s4*4];
            #pragma unroll
            for (int j = 0; j < 4; j++) bv[j] = *(ulonglong2*)&xs[(tx*4+j)*100 + s4*4];
            #pragma unroll
            for (int i = 0; i < 4; i++)
                #pragma unroll
                for (int j = 0; j < 4; j++) {
                    ffma2(pacc[i][j], av[i].x, bv[j].x);
                    ffma2(pacc[i][j], av[i].y, bv[j].y);
                }
        }
        #pragma unroll
        for (int j = 0; j < 7; j++) {
            int cell = tid + j*256;
            if (cell < CIN*VV) {
                int c = cell / VV, v = cell % VV;
                const float* row = &xs[c*100 + v];
                macc[j] += row[0] + row[25] + row[50] + row[75];
            }
        }
    }
    #pragma unroll
    for (int i = 0; i < 4; i++)
        #pragma unroll
        for (int j = 0; j < 4; j++) {
            float2 f = unpk(pacc[i][j]);
            g_Exxp[(size_t)n*CIN*CIN + (ty*4+i)*CIN + (tx*4+j)] = (double)(f.x + f.y);
        }
    #pragma unroll
    for (int j = 0; j < 7; j++) {
        int cell = tid + j*256;
        if (cell < CIN*VV) g_xm[n*CIN*VV + cell] = macc[j] * (1.0f/TT);
    }
}

// ---------------- K2b: reduce Exx partials over n; zero BN2 stats ----------------
__global__ void k2b_red() {
    int cell = blockIdx.x * blockDim.x + threadIdx.x;
    if (cell < CIN*CIN) {
        double s = 0.0;
        for (int n = 0; n < NN; n++) s += g_Exxp[(size_t)n*CIN*CIN + cell];
        g_Exx[cell] = s;
    }
    if (cell < CO) { g_s1[cell] = 0.0; g_s2[cell] = 0.0; }
}

// ---------------- K3: fold BN0 into linear; build transposed packed adjacency ----------------
__global__ void k3_prep(const float* __restrict__ dA, const float* __restrict__ Lw,
                        const float* __restrict__ Lb, const float* __restrict__ g0,
                        const float* __restrict__ be0) {
    __shared__ float Ex[CIN];
    for (int c = threadIdx.x; c < CIN; c += blockDim.x) {
        float s = 0.f;
        for (int n = 0; n < NN; n++) {
            const float* p = &g_xm[(n*CIN + c)*VV];
            for (int v = 0; v < VV; v++) s += p[v];
        }
        Ex[c] = s / (float)(NN*VV);
    }
    __syncthreads();

    for (int d = threadIdx.x; d < DD; d += blockDim.x) {
        float w[CIN];
        for (int c = 0; c < CIN; c++) w[c] = Lw[c*DD + d];
        double m1 = 0.0;
        for (int c = 0; c < CIN; c++) m1 += (double)w[c] * Ex[c];
        double quad = 0.0;
        for (int c1 = 0; c1 < CIN; c1++) {
            double tsum = 0.0;
            const double* row = &g_Exx[c1*CIN];
            for (int c2 = 0; c2 < CIN; c2++) tsum += (double)w[c2] * row[c2];
            quad += (double)w[c1] * (tsum / MTOT);
        }
        double var = quad - m1*m1;
        float  s   = g0[d] * rsqrtf((float)var + 1e-5f);
        g_bp[d] = be0[d] - s * (float)m1;
        for (int c = 0; c < CIN; c++) g_Wp[c*DD + d] = w[c] * s;
    }

    // nAT2[kg][w][p] = packed bf16x2 of (nA[kg][2p][w], nA[kg][2p+1][w]), pad v=25 -> 0
    for (int col = threadIdx.x; col < KK*GG*VV; col += blockDim.x) {
        int kg = col / VV, w = col % VV;
        float s = 0.f;
        for (int u = 0; u < VV; u++) s += dA[kg*VV*VV + u*VV + w];
        float inv = 1.0f / (s + 1e-3f);
        for (int p = 0; p < 13; p++) {
            float f0 = dA[kg*VV*VV + (2*p)*VV + w] * inv;
            float f1 = (2*p+1 < VV) ? dA[kg*VV*VV + (2*p+1)*VV + w] * inv : 0.f;
            g_nAT2[(kg*VV + w)*13 + p] = __floats2bfloat162_rn(f0, f1);
        }
    }
}

// ---------------- K4: x1/x2 = xm . w1/w2 + b ----------------
__global__ void k4_x12(const float* __restrict__ w1, const float* __restrict__ b1,
                       const float* __restrict__ w2, const float* __restrict__ b2) {
    int kn = blockIdx.x, k = kn / NN, n = kn % NN;
    __shared__ float xms[CIN*VV];
    for (int i = threadIdx.x; i < CIN*VV; i += blockDim.x) xms[i] = g_xm[n*CIN*VV + i];
    __syncthreads();
    for (int idx = threadIdx.x; idx < RR*VV; idx += blockDim.x) {
        int r = idx / VV, u = idx % VV;
        float a1 = b1[k*RR + r], a2 = b2[k*RR + r];
        const float* w1r = &w1[(k*RR + r)*CIN];
        const float* w2r = &w2[(k*RR + r)*CIN];
        for (int c = 0; c < CIN; c++) {
            float xv = xms[c*VV + u];
            a1 += xv * w1r[c];
            a2 += xv * w2r[c];
        }
        g_x1[(size_t)kn*RR*VV + idx] = a1;
        g_x2[(size_t)kn*RR*VV + idx] = a2;
    }
}

// ---------------- K5: attention matrices ----------------
__global__ void k5_att(const float* __restrict__ w4, const float* __restrict__ b4,
                       const float* __restrict__ A,  const float* __restrict__ alp) {
    int kn = blockIdx.x, k = kn / NN;
    __shared__ float x1s[RR*VV], x2s[RR*VV], w4s[CO*RR], b4s[CO], As[VV*VV];
    __shared__ float Ds[VV*VV*RR];
    for (int i = threadIdx.x; i < RR*VV; i += blockDim.x) {
        x1s[i] = g_x1[(size_t)kn*RR*VV + i];
        x2s[i] = g_x2[(size_t)kn*RR*VV + i];
    }
    for (int i = threadIdx.x; i < CO*RR;  i += blockDim.x) w4s[i] = w4[k*CO*RR + i];
    for (int i = threadIdx.x; i < CO;     i += blockDim.x) b4s[i] = b4[k*CO + i];
    for (int i = threadIdx.x; i < VV*VV;  i += blockDim.x) As[i]  = A[k*VV*VV + i];
    __syncthreads();
    for (int i = threadIdx.x; i < VV*VV*RR; i += blockDim.x) {
        int uw = i / RR, r = i % RR;
        int u = uw / VV, w = uw % VV;
        Ds[i] = tanhf(x1s[r*VV + u] - x2s[r*VV + w]);
    }
    __syncthreads();
    float alpha = alp[0];
    float* attp = g_att + (size_t)kn*CO*VV*VV;
    for (int i = threadIdx.x; i < CO*VV*VV; i += blockDim.x) {
        int c = i / (VV*VV), uw = i % (VV*VV);
        float s = 0.f;
        #pragma unroll
        for (int r = 0; r < RR; r++) s += w4s[c*RR + r] * Ds[uw*RR + r];
        attp[i] = alpha * (s + b4s[c]) + As[uw];
    }
}

// ---------------- K6: CTRGC branch (fused x3 GEMM + att contraction) ----------------
// grid (TT/8, NN), 512 thr. smem: xs[64][200] + x3s[64][200] + w3dup[64][64] ull
__global__ void __launch_bounds__(512, 1) k6_y(
        const float* __restrict__ x0, const float* __restrict__ w3,
        const float* __restrict__ b3) {
    extern __shared__ float sh[];
    float* xs  = sh;                         // 12800 f
    float* x3s = sh + 12800;                 // 12800 f, layout [c][u][t]
    ull*   w3d = (ull*)(sh + 25600);         // [64][64] duplicated pairs (8192 f)

    int n  = blockIdx.y;
    int tb = blockIdx.x * 8;
    int tid = threadIdx.x;

    for (int i = tid; i < CIN*50; i += 512) {
        int c = i / 50, q = i % 50;
        *(float4*)&xs[c*200 + q*4] =
            *(const float4*)&x0[((size_t)(n*CIN + c))*TVV + tb*VV + q*4];
    }

    ull ya[4][4];
    #pragma unroll
    for (int j = 0; j < 4; j++)
        #pragma unroll
        for (int e = 0; e < 4; e++) ya[j][e] = 0ull;

    for (int k = 0; k < KK; k++) {
        __syncthreads();
        for (int i = tid; i < CO*CIN; i += 512)
            w3d[i] = dup2(w3[k*CO*CIN + i]);
        __syncthreads();
        // x3 GEMM: 8 rows (c0 + r*8) per task, 4-wide s; tasks = 8*50 = 400
        if (tid < 400) {
            int c0 = tid / 50, q = tid % 50, s0 = q*4;
            ull a[8][2];
            #pragma unroll
            for (int r = 0; r < 8; r++) { a[r][0] = 0ull; a[r][1] = 0ull; }
            #pragma unroll 4
            for (int ci = 0; ci < CIN; ci++) {
                ulonglong2 xv = *(ulonglong2*)&xs[ci*200 + s0];
                #pragma unroll
                for (int r = 0; r < 8; r++) {
                    ull wd = w3d[(c0 + r*8)*CIN + ci];
                    ffma2(a[r][0], wd, xv.x);
                    ffma2(a[r][1], wd, xv.y);
                }
            }
            #pragma unroll
            for (int r = 0; r < 8; r++) {
                int c = c0 + r*8;
                float bb = b3[k*CO + c];
                float2 lo = unpk(a[r][0]), hi = unpk(a[r][1]);
                float vals[4] = {lo.x, lo.y, hi.x, hi.y};
                #pragma unroll
                for (int e = 0; e < 4; e++) {
                    int s = s0 + e, t = s / VV, v = s % VV;
                    x3s[c*200 + v*8 + t] = vals[e] + bb;
                }
            }
        }
        __syncthreads();
        // attention contraction: ya[t-pairs] += att[c][u][v] * x3s[c][u][:]
        const float* attp = g_att + (size_t)(k*NN + n)*CO*VV*VV;
        #pragma unroll
        for (int j = 0; j < 4; j++) {
            int p = j*512 + tid;
            if (p < CO*VV) {
                int c = p / VV, v = p % VV;
                const float* ac = attp + c*VV*VV + v;
                const float* xc = x3s + c*200;
                #pragma unroll 5
                for (int u = 0; u < VV; u++) {
                    ull ad = dup2(ac[u*VV]);
                    ulonglong2 xlo = *(ulonglong2*)&xc[u*8];
                    ulonglong2 xhi = *(ulonglong2*)&xc[u*8 + 4];
                    ffma2(ya[j][0], ad, xlo.x);
                    ffma2(ya[j][1], ad, xlo.y);
                    ffma2(ya[j][2], ad, xhi.x);
                    ffma2(ya[j][3], ad, xhi.y);
                }
            }
        }
    }
    #pragma unroll
    for (int j = 0; j < 4; j++) {
        int p = j*512 + tid;
        if (p < CO*VV) {
            int c = p / VV, v = p % VV;
            float2 f0 = unpk(ya[j][0]), f1 = unpk(ya[j][1]);
            float2 f2 = unpk(ya[j][2]), f3 = unpk(ya[j][3]);
            float tv[8] = {f0.x, f0.y, f1.x, f1.y, f2.x, f2.y, f3.x, f3.y};
            #pragma unroll
            for (int t = 0; t < 8; t++)
                g_y[((size_t)(n*CO + c))*TVV + (tb + t)*VV + v] = tv[t];
        }
    }
}

// ---------------- K7: fused linear + BN0 + decouple adjacency ----------------
// grid (TT/4, NN), 512 thr.
// smem: xs natural [64][100] | Wpd dup [64][192] ull | y192h bf16 [192][4][26]
//       | nAT2 [600][13] u32 | bps[192]
__global__ void __launch_bounds__(512, 1) k7_dec(const float* __restrict__ x0) {
    extern __shared__ float sh[];
    float* xs = sh;                                      // 6400 f
    ull*   Wpd = (ull*)(sh + 6400);                      // 24576 f
    __nv_bfloat16* y192h = (__nv_bfloat16*)(sh + 30976); // 9984 f
    unsigned* nAT2s = (unsigned*)(sh + 40960);           // 7800 f
    float* bps = sh + 48760;                             // 192 f

    int n  = blockIdx.y;
    int tb = blockIdx.x * 4;
    int tid = threadIdx.x;

    for (int i = tid; i < CIN*25; i += 512) {
        int c = i / 25, q = i % 25;
        *(float4*)&xs[c*100 + q*4] =
            *(const float4*)&x0[((size_t)(n*CIN + c))*TVV + tb*VV + q*4];
    }
    for (int i = tid; i < CIN*DD; i += 512)
        Wpd[i] = dup2(g_Wp[i]);                          // g_Wp is [c][192] linear
    for (int i = tid; i < DD; i += 512) bps[i] = g_bp[i];
    for (int i = tid; i < KK*GG*VV*13; i += 512)
        nAT2s[i] = ((const unsigned*)g_nAT2)[i];
    for (int i = tid; i < DD*4; i += 512) {              // zero v=25 pad slots
        int d = i >> 2, t = i & 3;
        y192h[d*104 + t*26 + 25] = __float2bfloat16(0.f);
    }
    __syncthreads();

    // stage 1: y192 GEMM; 12 rows (d0 + p*16) x 4 s per task; tasks = 16*25 = 400
    if (tid < 400) {
        int d0 = tid / 25, q = tid % 25, s0 = q*4;
        ull A[12][2];
        #pragma unroll
        for (int p = 0; p < 12; p++) { A[p][0] = 0ull; A[p][1] = 0ull; }
        #pragma unroll 4
        for (int ci = 0; ci < CIN; ci++) {
            ulonglong2 xv = *(ulonglong2*)&xs[ci*100 + s0];
            #pragma unroll
            for (int p = 0; p < 12; p++) {
                ull wd = Wpd[ci*DD + d0 + p*16];
                ffma2(A[p][0], wd, xv.x);
                ffma2(A[p][1], wd, xv.y);
            }
        }
        #pragma unroll
        for (int p = 0; p < 12; p++) {
            int d = d0 + p*16;
            float bb = bps[d];
            float2 lo = unpk(A[p][0]), hi = unpk(A[p][1]);
            float vals[4] = {lo.x, lo.y, hi.x, hi.y};
            #pragma unroll
            for (int e = 0; e < 4; e++) {
                int s = s0 + e, t = s / VV, v = s % VV;
                y192h[d*104 + t*26 + v] = __float2bfloat16(vals[e] + bb);
            }
        }
    }
    __syncthreads();

    // stage 2: xdec[c][t][w] = sum_k sum_v y192[kc][t][v] * nAT[kg][w][v]  (bf16x2)
    const unsigned* yu = (const unsigned*)y192h;
    for (int rep = 0; rep < 7; rep++) {
        int i = rep*512 + tid;
        if (i >= 32*100) break;
        int c0 = i / 100, tw = i % 100, t = tw / VV, w = tw % VV;
        int g = c0 & 7;
        unsigned h0 = 0, h1 = 0;
        #pragma unroll
        for (int k = 0; k < KK; k++) {
            const unsigned* nr = nAT2s + ((k*GG + g)*VV + w)*13;
            const unsigned* y0 = yu + (k*CO + c0)*52 + t*13;
            const unsigned* y1 = yu + (k*CO + c0 + 32)*52 + t*13;
            #pragma unroll
            for (int p = 0; p < 13; p++) {
                unsigned av = nr[p];
                hfma2(h0, av, y0[p]);
                hfma2(h1, av, y1[p]);
            }
        }
        __nv_bfloat162 hb0 = *(__nv_bfloat162*)&h0;
        __nv_bfloat162 hb1 = *(__nv_bfloat162*)&h1;
        g_xdec[((size_t)(n*CO + c0))*TVV + tb*VV + tw] =
            __low2float(hb0) + __high2float(hb0);
        g_xdec[((size_t)(n*CO + c0 + 32))*TVV + tb*VV + tw] =
            __low2float(hb1) + __high2float(hb1);
    }
}

// ---------------- K8: ensemble GEMM + BN2 partial stats ----------------
// grid (TT/8, NN), 512 thr. Each warp owns o-quad (wid, wid+16, wid+32, wid+48).
__global__ void __launch_bounds__(512, 1) k8_ens(
        const float* __restrict__ ew, const float* __restrict__ eb) {
    extern __shared__ float sh[];
    float* xd  = sh;                   // 12800 f
    float* ys  = sh + 12800;           // 12800 f
    ull*   ewd = (ull*)(sh + 25600);   // [64][128] dup (16384 f)
    float* s1s = sh + 41984;           // 64
    float* s2s = sh + 42048;           // 64

    int n  = blockIdx.y;
    int tb = blockIdx.x * 8;
    int tid = threadIdx.x;
    int wid = tid >> 5, lane = tid & 31;

    for (int i = tid; i < CIN*50; i += 512) {
        int c = i / 50, q = i % 50;
        size_t off = ((size_t)(n*CO + c))*TVV + tb*VV + q*4;
        *(float4*)&xd[c*200 + q*4] = *(const float4*)&g_xdec[off];
        *(float4*)&ys[c*200 + q*4] = *(const float4*)&g_y[off];
    }
    for (int i = tid; i < CO*2*CO; i += 512)
        ewd[i] = dup2(ew[i]);
    __syncthreads();

    int o[4];  ull bd[4];
    float ls1[4], ls2[4];
    #pragma unroll
    for (int r = 0; r < 4; r++) {
        o[r] = wid + r*16;
        bd[r] = dup2(eb[o[r]]);
        ls1[r] = 0.f; ls2[r] = 0.f;
    }

    for (int rep = 0; rep < 2; rep++) {
        int q = lane + rep*32;
        if (q >= 50) break;
        int s0 = q*4;
        ull A[4][2];
        #pragma unroll
        for (int r = 0; r < 4; r++) { A[r][0] = bd[r]; A[r][1] = bd[r]; }
        #pragma unroll 4
        for (int c = 0; c < CIN; c++) {
            ulonglong2 xv = *(ulonglong2*)&xd[c*200 + s0];
            ulonglong2 yv = *(ulonglong2*)&ys[c*200 + s0];
            #pragma unroll
            for (int r = 0; r < 4; r++) {
                ull wx = ewd[o[r]*128 + c];
                ull wy = ewd[o[r]*128 + 64 + c];
                ffma2(A[r][0], wx, xv.x);
                ffma2(A[r][0], wy, yv.x);
                ffma2(A[r][1], wx, xv.y);
                ffma2(A[r][1], wy, yv.y);
            }
        }
        #pragma unroll
        for (int r = 0; r < 4; r++) {
            float2 lo = unpk(A[r][0]), hi = unpk(A[r][1]);
            float4 res = make_float4(lo.x, lo.y, hi.x, hi.y);
            *(float4*)&g_ens[((size_t)(n*CO + o[r]))*TVV + tb*VV + s0] = res;
            ls1[r] += res.x + res.y + res.z + res.w;
            ls2[r] += res.x*res.x + res.y*res.y + res.z*res.z + res.w*res.w;
        }
    }
    // width-32 warp reduction; all lanes of a warp share the same o-quad
    #pragma unroll
    for (int off = 16; off; off >>= 1) {
        #pragma unroll
        for (int r = 0; r < 4; r++) {
            ls1[r] += __shfl_down_sync(0xffffffffu, ls1[r], off);
            ls2[r] += __shfl_down_sync(0xffffffffu, ls2[r], off);
        }
    }
    if (lane == 0) {
        #pragma unroll
        for (int r = 0; r < 4; r++) { s1s[o[r]] = ls1[r]; s2s[o[r]] = ls2[r]; }
    }
    __syncthreads();
    if (tid < CO) {
        atomicAdd(&g_s1[tid], (double)s1s[tid]);
        atomicAdd(&g_s2[tid], (double)s2s[tid]);
    }
}

// ---------------- K9: finalize BN2 ----------------
__global__ void k9_fin(const float* __restrict__ bng, const float* __restrict__ bnb) {
    int o = threadIdx.x;
    if (o < CO) {
        double mu  = g_s1[o] / MTOT;
        double var = g_s2[o] / MTOT - mu*mu;
        float sc = bng[o] * rsqrtf((float)var + 1e-5f);
        g_scale2[o] = sc;
        g_shift2[o] = bnb[o] - (float)mu * sc;
    }
}

// ---------------- K10: BN2 apply + residual + ReLU ----------------
__global__ void k10_out(const float* __restrict__ x0, float* __restrict__ out) {
    size_t total4 = (size_t)NN*CO*TT*VV / 4;
    for (size_t i4 = (size_t)blockIdx.x*blockDim.x + threadIdx.x; i4 < total4;
         i4 += (size_t)gridDim.x*blockDim.x) {
        size_t i = i4 * 4;
        int o = (int)((i / TVV) & (CO - 1));
        float sc = g_scale2[o], shf = g_shift2[o];
        float4 e = *(const float4*)&g_ens[i];
        float4 x = *(const float4*)&x0[i];
        float4 r;
        r.x = fmaxf(e.x*sc + shf + x.x, 0.f);
        r.y = fmaxf(e.y*sc + shf + x.y, 0.f);
        r.z = fmaxf(e.z*sc + shf + x.z, 0.f);
        r.w = fmaxf(e.w*sc + shf + x.w, 0.f);
        *(float4*)&out[i] = r;
    }
}

// ---------------- launch ----------------
extern "C" void kernel_launch(void* const* d_in, const int* in_sizes, int n_in,
                              void* d_out, int out_size) {
    const float* x0  = (const float*)d_in[0];
    const float* dA  = (const float*)d_in[1];
    const float* A   = (const float*)d_in[2];
    const float* alp = (const float*)d_in[3];
    const float* w1  = (const float*)d_in[4];
    const float* b1  = (const float*)d_in[5];
    const float* w2  = (const float*)d_in[6];
    const float* b2  = (const float*)d_in[7];
    const float* w3  = (const float*)d_in[8];
    const float* b3  = (const float*)d_in[9];
    const float* w4  = (const float*)d_in[10];
    const float* b4  = (const float*)d_in[11];
    const float* Lw  = (const float*)d_in[12];
    const float* Lb  = (const float*)d_in[13];
    const float* g0  = (const float*)d_in[14];
    const float* be0 = (const float*)d_in[15];
    const float* ew  = (const float*)d_in[16];
    const float* eb  = (const float*)d_in[17];
    const float* bng = (const float*)d_in[18];
    const float* bnb = (const float*)d_in[19];
    float* out = (float*)d_out;

    const int smem_k6 = (12800 + 12800 + 8192) * 4;            // 135168
    const int smem_k7 = 48952 * 4;                              // 195808
    const int smem_k8 = (12800 + 12800 + 16384 + 128) * 4;      // 168448

    cudaFuncSetAttribute(k6_y,   cudaFuncAttributeMaxDynamicSharedMemorySize, smem_k6);
    cudaFuncSetAttribute(k7_dec, cudaFuncAttributeMaxDynamicSharedMemorySize, smem_k7);
    cudaFuncSetAttribute(k8_ens, cudaFuncAttributeMaxDynamicSharedMemorySize, smem_k8);

    // k6 placed 4th so the ncu sampled launch is the biggest kernel this round
    k2_exx <<<NN, 256>>>(x0);
    k4_x12 <<<KK*NN, 256>>>(w1, b1, w2, b2);
    k5_att <<<KK*NN, 256>>>(w4, b4, A, alp);
    k6_y   <<<dim3(TT/8, NN), 512, smem_k6>>>(x0, w3, b3);
    k2b_red<<<16, 256>>>();
    k3_prep<<<1, 256>>>(dA, Lw, Lb, g0, be0);
    k7_dec <<<dim3(TT/4, NN), 512, smem_k7>>>(x0);
    k8_ens <<<dim3(TT/8, NN), 512, smem_k8>>>(ew, eb);
    k9_fin <<<1, 64>>>(bng, bnb);
    k10_out<<<4096, 256>>>(x0, out);
}